// round 1
// baseline (speedup 1.0000x reference)
#include <cuda_runtime.h>
#include <cuda_bf16.h>

#define TABLE_SCALE 1024.0f   // 2^10
#define TABLE_MAX   4095      // TABLE_SIZE - 1

__device__ __forceinline__ float secgelu_one(float x, const float* __restrict__ table) {
    float a = fabsf(x);
    int c = (int)(a * TABLE_SCALE);          // truncation toward zero, a >= 0
    c = min(c, TABLE_MAX);
    float relu_x = x >= 0.0f ? x : 0.0f;
    return relu_x - __ldg(table + c);
}

__global__ void __launch_bounds__(256) SecGELU_kernel(
    const float4* __restrict__ x,
    const float* __restrict__ table,
    float4* __restrict__ out,
    int n4)
{
    int i = blockIdx.x * blockDim.x + threadIdx.x;
    if (i >= n4) return;
    float4 v = x[i];
    float4 r;
    r.x = secgelu_one(v.x, table);
    r.y = secgelu_one(v.y, table);
    r.z = secgelu_one(v.z, table);
    r.w = secgelu_one(v.w, table);
    out[i] = r;
}

// Tail handler for n not divisible by 4 (not needed for 2^26, but safe).
__global__ void SecGELU_tail(
    const float* __restrict__ x,
    const float* __restrict__ table,
    float* __restrict__ out,
    int start, int n)
{
    int i = start + blockIdx.x * blockDim.x + threadIdx.x;
    if (i >= n) return;
    out[i] = secgelu_one(x[i], table);
}

extern "C" void kernel_launch(void* const* d_in, const int* in_sizes, int n_in,
                              void* d_out, int out_size) {
    const float* x     = (const float*)d_in[0];
    const float* table = (const float*)d_in[1];
    float* out = (float*)d_out;

    int n  = in_sizes[0];
    int n4 = n >> 2;

    if (n4 > 0) {
        int threads = 256;
        int blocks = (n4 + threads - 1) / threads;
        SecGELU_kernel<<<blocks, threads>>>(
            (const float4*)x, table, (float4*)out, n4);
    }
    int rem = n - (n4 << 2);
    if (rem > 0) {
        SecGELU_tail<<<1, 32>>>(x, table, out, n4 << 2, n);
    }
}

// round 2
// speedup vs baseline: 1.1978x; 1.1978x over previous
#include <cuda_runtime.h>
#include <cuda_bf16.h>

#define TABLE_SCALE 1024.0f   // 2^10
#define TABLE_MAX   4095      // TABLE_SIZE - 1
#define UNROLL 4

__device__ __forceinline__ float secgelu_one(float x, const float* __restrict__ table) {
    float a = fabsf(x);
    int c = (int)(a * TABLE_SCALE);          // truncation toward zero, a >= 0
    c = min(c, TABLE_MAX);
    float relu_x = x >= 0.0f ? x : 0.0f;
    return relu_x - __ldg(table + c);
}

__device__ __forceinline__ float4 secgelu_vec4(float4 v, const float* __restrict__ table) {
    float4 r;
    r.x = secgelu_one(v.x, table);
    r.y = secgelu_one(v.y, table);
    r.z = secgelu_one(v.z, table);
    r.w = secgelu_one(v.w, table);
    return r;
}

// Each thread processes UNROLL float4s, front-batching the independent
// streaming loads so MLP_p1 = UNROLL (hides DRAM latency). Loads/stores use
// .cs streaming hints: the 512 MiB of x/out traffic shouldn't pollute L2,
// while the 16 KB table (plain __ldg) stays L1/L2 resident.
__global__ void __launch_bounds__(256) SecGELU_kernel(
    const float4* __restrict__ x,
    const float* __restrict__ table,
    float4* __restrict__ out,
    int n4)
{
    int base = blockIdx.x * (blockDim.x * UNROLL) + threadIdx.x;

    float4 v[UNROLL];
    bool full = (base + (UNROLL - 1) * blockDim.x) < n4;

    if (full) {
        #pragma unroll
        for (int k = 0; k < UNROLL; k++)
            v[k] = __ldcs(x + base + k * blockDim.x);   // front-batched, independent

        #pragma unroll
        for (int k = 0; k < UNROLL; k++)
            __stcs(out + base + k * blockDim.x, secgelu_vec4(v[k], table));
    } else {
        #pragma unroll
        for (int k = 0; k < UNROLL; k++) {
            int i = base + k * blockDim.x;
            if (i < n4) {
                float4 t = __ldcs(x + i);
                __stcs(out + i, secgelu_vec4(t, table));
            }
        }
    }
}

// Tail handler for n not divisible by 4 (not needed for 2^26, but safe).
__global__ void SecGELU_tail(
    const float* __restrict__ x,
    const float* __restrict__ table,
    float* __restrict__ out,
    int start, int n)
{
    int i = start + blockIdx.x * blockDim.x + threadIdx.x;
    if (i >= n) return;
    out[i] = secgelu_one(x[i], table);
}

extern "C" void kernel_launch(void* const* d_in, const int* in_sizes, int n_in,
                              void* d_out, int out_size) {
    const float* x     = (const float*)d_in[0];
    const float* table = (const float*)d_in[1];
    float* out = (float*)d_out;

    int n  = in_sizes[0];
    int n4 = n >> 2;

    if (n4 > 0) {
        int threads = 256;
        int per_block = threads * UNROLL;
        int blocks = (n4 + per_block - 1) / per_block;
        SecGELU_kernel<<<blocks, threads>>>(
            (const float4*)x, table, (float4*)out, n4);
    }
    int rem = n - (n4 << 2);
    if (rem > 0) {
        SecGELU_tail<<<1, 32>>>(x, table, out, n4 << 2, n);
    }
}